// round 16
// baseline (speedup 1.0000x reference)
#include <cuda_runtime.h>
#include <math.h>

// Problem constants (fixed by the reference)
#define POOL   100
#define NTASKS 10
#define NB_PT  (POOL / NTASKS)       // 10
#define PLEN   8
#define EMBD   768
#define BATCH  512
#define ED4    (EMBD / 4)            // 192

// sim: 320 active blocks (k<task_end), 16 warps each, one batch row per warp
#define SIM_G       32
#define SIM_THREADS 512
#define SIM_ROWS    (BATCH / SIM_G)  // 16

// mega pmt: 2 batch rows x half output range per block -> 512 blocks
#define BPB         2
#define SPLIT       2
#define PMT_BLOCKS  ((BATCH / BPB) * SPLIT)       // 512
#define CHUNK4      ((PLEN * ED4) / SPLIT)        // 768 float4 per block
#define OUT_PER_T   (CHUNK4 / 256)                // 3 float4 per thread
#define COPY_BLOCKS 2560

// Scratch (allocation-free per harness rules)
__device__ float g_sim[BATCH * POOL];

// ---------------------------------------------------------------------------
// Kernel A: fused diag + sim. grid=(32, POOL), block=512 (16 warps).
// diag[k] built once per block in smem; one batch row per warp.
// 320 active blocks -> no straggler tail (2.16 CTAs/SM, 4-CTA slots).
// ---------------------------------------------------------------------------
__global__ void __launch_bounds__(SIM_THREADS) sim_fused_kernel(
        const float* __restrict__ x_querry,
        const float* __restrict__ e_a,
        const float* __restrict__ e_p,
        const int*   __restrict__ task_id_p) {
    const int task_end = (*task_id_p + 1) * NB_PT;
    const int k = blockIdx.y;
    if (k >= task_end) return;

    __shared__ float s_diag[EMBD];
    __shared__ float s_ea[EMBD];

    // Phase 1: diag + ea into smem
    const float* epk = e_p + (size_t)k * PLEN * EMBD;
    for (int d = threadIdx.x; d < EMBD; d += SIM_THREADS) {
        float acc = 0.f;
#pragma unroll
        for (int l = 0; l < PLEN; l++) {
            float v = epk[l * EMBD + d];
            acc += v * v;
        }
        s_diag[d] = acc;
        s_ea[d]   = e_a[(size_t)k * EMBD + d];
    }
    __syncthreads();

    // Phase 2: one warp per batch row
    const int warp = threadIdx.x >> 5;
    const int lane = threadIdx.x & 31;
    const int b = blockIdx.x * SIM_ROWS + warp;
    const int row = POOL - task_end + k;

    const float4* xq4 = (const float4*)(x_querry + ((size_t)b * POOL + row) * EMBD);
    const float4* ea4 = (const float4*)s_ea;
    const float4* dg4 = (const float4*)s_diag;

    float s1 = 0.f, s2 = 0.f, s3 = 0.f;
#pragma unroll
    for (int j = 0; j < ED4 / 32; j++) {   // 6 iterations
        int idx = lane + j * 32;
        float4 x = xq4[idx];
        float4 e = ea4[idx];
        float4 g = dg4[idx];
        float a, aa;
        a = x.x * e.x; aa = a * a; s3 += aa; s1 += aa * g.x; s2 += aa * g.x * g.x;
        a = x.y * e.y; aa = a * a; s3 += aa; s1 += aa * g.y; s2 += aa * g.y * g.y;
        a = x.z * e.z; aa = a * a; s3 += aa; s1 += aa * g.z; s2 += aa * g.z * g.z;
        a = x.w * e.w; aa = a * a; s3 += aa; s1 += aa * g.w; s2 += aa * g.w * g.w;
    }
#pragma unroll
    for (int o = 16; o > 0; o >>= 1) {
        s1 += __shfl_down_sync(0xFFFFFFFFu, s1, o);
        s2 += __shfl_down_sync(0xFFFFFFFFu, s2, o);
        s3 += __shfl_down_sync(0xFFFFFFFFu, s3, o);
    }
    if (lane == 0) {
        const float eps = 1e-12f;
        float n1 = fmaxf(sqrtf(s2), eps);
        float n2 = fmaxf(sqrtf(s3), eps);
        g_sim[(size_t)b * POOL + k] = s1 / (n1 * n2);
    }
}

// ---------------------------------------------------------------------------
// Kernel B: mega.
//   blocks [0,512): pmt — 2 batch rows x half output range each; every e_p
//                   float4 read feeds 2 accumulators (L2 traffic halved).
//   blocks [512, 3072): streaming copy.
// ---------------------------------------------------------------------------
__global__ void __launch_bounds__(256) mega_kernel(
        const float* __restrict__ e_p,
        const float* __restrict__ x_block,
        const int*   __restrict__ task_id_p,
        float* __restrict__ out,
        size_t xb_float4s) {
    if (blockIdx.x < PMT_BLOCKS) {
        // ---- einsum: int_pmt[b,l,d] = sum_k sim[b,k] * e_p[k,l,d] ----
        const int task_end = (*task_id_p + 1) * NB_PT;
        const int g  = blockIdx.x / SPLIT;      // batch pair index
        const int sp = blockIdx.x % SPLIT;      // output half
        const int b0 = g * BPB;
        const int tid = threadIdx.x;

        __shared__ float s_sim[BPB][POOL];
        for (int i = tid; i < BPB * POOL; i += 256)
            s_sim[i / POOL][i % POOL] =
                g_sim[(size_t)(b0 + i / POOL) * POOL + (i % POOL)];
        __syncthreads();

        const float4* ep4 = (const float4*)e_p;
        const int base4 = sp * CHUNK4;

        float4 acc[BPB][OUT_PER_T];
#pragma unroll
        for (int bs = 0; bs < BPB; bs++)
#pragma unroll
            for (int j = 0; j < OUT_PER_T; j++)
                acc[bs][j] = make_float4(0.f, 0.f, 0.f, 0.f);

        for (int kk = 0; kk < task_end; kk++) {
            float sv0 = s_sim[0][kk];
            float sv1 = s_sim[1][kk];
#pragma unroll
            for (int j = 0; j < OUT_PER_T; j++) {
                int idx = base4 + tid + j * 256;
                float4 v = ep4[(size_t)kk * PLEN * ED4 + idx];
                acc[0][j].x += sv0 * v.x; acc[0][j].y += sv0 * v.y;
                acc[0][j].z += sv0 * v.z; acc[0][j].w += sv0 * v.w;
                acc[1][j].x += sv1 * v.x; acc[1][j].y += sv1 * v.y;
                acc[1][j].z += sv1 * v.z; acc[1][j].w += sv1 * v.w;
            }
        }

        const size_t KEY4 = (size_t)BATCH * (PLEN / 2) * ED4;
#pragma unroll
        for (int j = 0; j < OUT_PER_T; j++) {
            int idx = base4 + tid + j * 256;
            int l  = idx / ED4;
            int d4 = idx % ED4;
#pragma unroll
            for (int bs = 0; bs < BPB; bs++) {
                int b = b0 + bs;
                float4* o4;
                if (l < PLEN / 2)
                    o4 = (float4*)out + ((size_t)b * (PLEN / 2) + l) * ED4 + d4;
                else
                    o4 = (float4*)out + KEY4 +
                         ((size_t)b * (PLEN / 2) + (l - PLEN / 2)) * ED4 + d4;
                *o4 = acc[bs][j];
            }
        }
    } else {
        // ---- streaming copy: x_block -> out tail ----
        const float4* src = (const float4*)x_block;
        float4* dst = (float4*)(out + (size_t)BATCH * PLEN * EMBD);

        const size_t stride = (size_t)COPY_BLOCKS * 256;
        size_t i = (size_t)(blockIdx.x - PMT_BLOCKS) * 256 + threadIdx.x;

        for (; i + 3 * stride < xb_float4s; i += 4 * stride) {
            float4 v0 = __ldcs(src + i);
            float4 v1 = __ldcs(src + i + stride);
            float4 v2 = __ldcs(src + i + 2 * stride);
            float4 v3 = __ldcs(src + i + 3 * stride);
            __stcs(dst + i,              v0);
            __stcs(dst + i + stride,     v1);
            __stcs(dst + i + 2 * stride, v2);
            __stcs(dst + i + 3 * stride, v3);
        }
        for (; i < xb_float4s; i += stride)
            __stcs(dst + i, __ldcs(src + i));
    }
}

// ---------------------------------------------------------------------------
// Launch — two kernels: sim_fused -> mega(pmt+copy).
// Inputs (metadata order): x_querry, x_block, e_a, e_p, idx, task_id
// ---------------------------------------------------------------------------
extern "C" void kernel_launch(void* const* d_in, const int* in_sizes, int n_in,
                              void* d_out, int out_size) {
    const float* x_querry = (const float*)d_in[0];
    const float* x_block  = (const float*)d_in[1];
    const float* e_a      = (const float*)d_in[2];
    const float* e_p      = (const float*)d_in[3];
    const int*   task_id  = (const int*)d_in[5];
    float* out = (float*)d_out;

    dim3 sim_grid(SIM_G, POOL);
    sim_fused_kernel<<<sim_grid, SIM_THREADS>>>(x_querry, e_a, e_p, task_id);

    size_t xb_float4s = (size_t)in_sizes[1] / 4;
    mega_kernel<<<PMT_BLOCKS + COPY_BLOCKS, 256>>>(
        e_p, x_block, task_id, out, xb_float4s);
}